// round 12
// baseline (speedup 1.0000x reference)
#include <cuda_runtime.h>
#include <math.h>
#include <stdint.h>

#define MAXN 8192
#define MAXM 1024          // max valid boxes (E[M]~800, sigma~27; 8+ sigma headroom)
#define W    16            // 64-bit words per suppression row (MAXM/64)

typedef unsigned long long u64;

__device__ float4 g_boxes[MAXN];
__device__ u64 g_keys[MAXM];     // compacted valid keys (unsorted)
__device__ u64 g_skeys[MAXM];    // sorted keys
__device__ float4 g_sboxes[MAXM];
__device__ u64 g_sup[MAXM * W];  // suppression bit matrix (upper triangular)
__device__ u64 g_allOR[W];       // OR of all rows (cols with a suppressor)
__device__ u64 g_rowNZ[W];       // rows with any nonzero word
__device__ int g_count;          // zero-init at load; k_scan resets everything

// ---------------------------------------------------------------------------
// K1: per-box scale/mask, xyxy+round, compact valid keys, zero the output.
// ---------------------------------------------------------------------------
__global__ void k_prep(const float* __restrict__ o0, const float* __restrict__ o1,
                       int P0, int P1, float* __restrict__ out, int out_size, int N) {
    int n = blockIdx.x * blockDim.x + threadIdx.x;
    int stride = gridDim.x * blockDim.x;
    for (int t = n; t < out_size; t += stride) out[t] = 0.0f;
    if (n >= N) return;

    const float* src;
    int P, loc;
    int A0 = P0 * P0;
    if (n < A0) { src = o0; P = P0; loc = n; }
    else        { src = o1; P = P1; loc = n - A0; }
    int i = loc / P, j = loc - i * P;
    int A = P * P;

    float prob = src[0 * A + loc];
    float x1   = src[1 * A + loc];
    float x2   = src[2 * A + loc];
    float x3   = src[3 * A + loc];
    float x4   = src[4 * A + loc];

    float xps = 640.0f / (float)P;   // exact: 16 or 8
    float yps = 480.0f / (float)P;   // exact: 12 or 6
    bool m = prob > 0.9f;

    float c1 = m ? (x1 * xps + (float)i * xps) : x1;
    float c2 = m ? (x2 * yps + (float)j * yps) : x2;
    float c3 = m ? (x3 * 640.0f) : x3;
    float c4 = m ? (x4 * 480.0f) : x4;

    float X1 = rintf(c1);
    float Y1 = rintf(c2);
    float X2 = rintf(c3 + c1);
    float Y2 = rintf(c4 + c2);

    g_boxes[n] = make_float4(X1, Y1, X2, Y2);

    if (m) {
        int pos = atomicAdd(&g_count, 1);
        if (pos < MAXM) {
            unsigned int hi = 0xFFFFFFFFu - __float_as_uint(prob);  // descending score
            g_keys[pos] = ((u64)hi << 32) | (unsigned int)n;        // tie: asc idx
        }
    }
}

// ---------------------------------------------------------------------------
// K2: single-block hybrid bitonic sort (shfl for j<=16, smem for j>=32).
// ---------------------------------------------------------------------------
__global__ void __launch_bounds__(1024, 1) k_sort() {
    __shared__ u64 keys[MAXM];
    const int tid = threadIdx.x;

    int M = g_count; if (M > MAXM) M = MAXM;

    u64 v = (tid < M) ? g_keys[tid] : 0xFFFFFFFFFFFFFFFFull;

#pragma unroll
    for (int k = 2; k <= 32; k <<= 1) {
#pragma unroll
        for (int j = k >> 1; j >= 1; j >>= 1) {
            u64 p = __shfl_xor_sync(0xFFFFFFFFu, v, j);
            bool up = ((tid & k) == 0);
            bool keepmin = (((tid & j) == 0) == up);
            u64 lo = v < p ? v : p;
            u64 hi = v < p ? p : v;
            v = keepmin ? lo : hi;
        }
    }
    keys[tid] = v;
    __syncthreads();

    for (int k = 64; k <= 1024; k <<= 1) {
        for (int j = k >> 1; j >= 32; j >>= 1) {
            int ixj = tid ^ j;
            if (ixj > tid) {
                u64 a = keys[tid], b = keys[ixj];
                bool up = ((tid & k) == 0);
                if ((a > b) == up) { keys[tid] = b; keys[ixj] = a; }
            }
            __syncthreads();
        }
        v = keys[tid];
        bool up = ((tid & k) == 0);
#pragma unroll
        for (int j = 16; j >= 1; j >>= 1) {
            u64 p = __shfl_xor_sync(0xFFFFFFFFu, v, j);
            bool keepmin = (((tid & j) == 0) == up);
            u64 lo = v < p ? v : p;
            u64 hi = v < p ? p : v;
            v = keepmin ? lo : hi;
        }
        keys[tid] = v;
        __syncthreads();
    }

    if (tid < M) {
        u64 kk = keys[tid];
        g_skeys[tid] = kk;
        g_sboxes[tid] = g_boxes[(unsigned int)(kk & 0xFFFFFFFFu)];
    }
}

// ---------------------------------------------------------------------------
// K3: suppression bit matrix (upper triangular) + allOR/rowNZ summaries.
// Exact iou>0.5 via inter > 0.5*uni (all quantities integer-valued fp32).
// ---------------------------------------------------------------------------
__global__ void k_matrix() {
    int M = g_count; if (M > MAXM) M = MAXM;
    int t = blockIdx.x * blockDim.x + threadIdx.x;
    int i  = t >> 4;       // row
    int jw = t & (W - 1);  // word within row
    if (i >= M) return;

    int jbase = jw << 6;
    u64 word = 0;
    if (jbase + 64 > i + 1 && jbase < M) {
        float4 bi = g_sboxes[i];
        float ai = (bi.z - bi.x) * (bi.w - bi.y);
        int jend = min(jbase + 64, M);
        for (int j = max(jbase, i + 1); j < jend; ++j) {
            float4 bj = g_sboxes[j];
            float iw = fminf(bi.z, bj.z) - fmaxf(bi.x, bj.x);
            float ih = fminf(bi.w, bj.w) - fmaxf(bi.y, bj.y);
            iw = fmaxf(iw, 0.0f);
            ih = fmaxf(ih, 0.0f);
            float inter = iw * ih;
            float aj = (bj.z - bj.x) * (bj.w - bj.y);
            float uni = ai + aj - inter;
            if (uni > 0.0f && inter > 0.5f * uni)
                word |= 1ull << (j - jbase);
        }
    }
    g_sup[t] = word;
    if (word) {
        atomicOr(&g_allOR[jw], word);
        atomicOr(&g_rowNZ[i >> 6], 1ull << (i & 63));
    }
}

// ---------------------------------------------------------------------------
// K4: parallel peeling of the greedy fixpoint + serial residue.
// kept: no possible live suppressor. remK: OR of kept rows (= removed set).
// Peeling is exact (relation is a DAG: j suppresses i => j < i); serial loop
// finishes any deep-chain leftovers in ascending order. Emit; reset state.
// ---------------------------------------------------------------------------
__device__ __forceinline__ u64 valid_mask(int w, int M) {
    int nb = M - (w << 6);
    return (nb <= 0) ? 0ull : ((nb >= 64) ? ~0ull : ((1ull << nb) - 1ull));
}

extern __shared__ u64 sup_s[];  // MAXM*W u64 = 128KB (only nonzero rows written)
__global__ void __launch_bounds__(1024, 1) k_scan(float* __restrict__ out) {
    __shared__ u64 rowNZ_s[W], remK_s[W], kept_s[W], unkOR_s[W], newK_s[W], rem_s[W];
    __shared__ int done_s;
    const int tid = threadIdx.x;
    const int bd  = 1024;
    const int w16 = tid & 15;

    int M = g_count; if (M > MAXM) M = MAXM;
    int tot = M * W;

    if (tid < W) {
        rowNZ_s[tid] = g_rowNZ[tid];
        remK_s[tid] = 0;
        kept_s[tid] = 0;
        unkOR_s[tid] = 0;
    }
    if (tid == 0) done_s = 0;
    __syncthreads();

    // Stage nonzero rows into smem; fold round-0 unkOR (all boxes unknown).
    u64 myU = 0;
    for (int q = tid; q < tot; q += bd) {
        int ri = q >> 4;
        if ((rowNZ_s[ri >> 6] >> (ri & 63)) & 1ull) {
            u64 vv = g_sup[q];
            sup_s[q] = vv;
            myU |= vv;
        }
    }
    myU |= __shfl_xor_sync(0xFFFFFFFFu, myU, 16);
    if ((tid & 31) < 16) atomicOr(&unkOR_s[w16], myU);
    __syncthreads();

    // Peeling rounds (round 0's unkOR precomputed above).
    for (int r = 0; r < 6 && !done_s; ++r) {
        if (r > 0) {
            // recompute unkOR over current unknown nonzero rows
            if (tid < W) unkOR_s[tid] = 0;
            __syncthreads();
            u64 mu = 0;
            for (int q = tid; q < tot; q += bd) {
                int ri = q >> 4;
                int rw = ri >> 6, rb = ri & 63;
                bool unk = !((kept_s[rw] >> rb) & 1ull) && !((remK_s[rw] >> rb) & 1ull);
                if (unk && ((rowNZ_s[rw] >> rb) & 1ull)) mu |= sup_s[q];
            }
            mu |= __shfl_xor_sync(0xFFFFFFFFu, mu, 16);
            if ((tid & 31) < 16) atomicOr(&unkOR_s[w16], mu);
            __syncthreads();
        }

        // Classify: unknown with no live suppressor -> kept.
        if (tid < W) {
            u64 vw = valid_mask(tid, M);
            u64 unknown = vw & ~kept_s[tid] & ~remK_s[tid];
            u64 nk = unknown & ~unkOR_s[tid];   // remK already excluded
            newK_s[tid] = nk;
            kept_s[tid] |= nk;
        }
        __syncthreads();

        // Fold newly-kept rows into remK.
        u64 mr = 0;
        for (int q = tid; q < tot; q += bd) {
            int ri = q >> 4;
            int rw = ri >> 6, rb = ri & 63;
            if (((newK_s[rw] >> rb) & 1ull) && ((rowNZ_s[rw] >> rb) & 1ull))
                mr |= sup_s[q];
        }
        mr |= __shfl_xor_sync(0xFFFFFFFFu, mr, 16);
        if ((tid & 31) < 16) atomicOr(&remK_s[w16], mr);
        __syncthreads();

        // Termination: any unknowns left?
        if (tid < 32) {
            u64 u = (tid < W)
                  ? (valid_mask(tid, M) & ~kept_s[tid] & ~remK_s[tid]) : 0ull;
            unsigned any = __ballot_sync(0xFFFFFFFFu, u != 0ull);
            if (tid == 0) done_s = (any == 0u);
        }
        __syncthreads();
    }

    // Serial residue: leftover unknowns, ascending, exact greedy.
    if (tid < 32) {
        const int lane = tid;
        const int lw   = lane & 15;
        u64 rem_own = (lane < W) ? remK_s[lane] : 0;
        int nwords = (M + 63) >> 6;

        for (int w = 0; w < nwords; ++w) {
            u64 remw = __shfl_sync(0xFFFFFFFFu, rem_own, w);
            u64 cand = valid_mask(w, M) & ~kept_s[w] & ~remw & rowNZ_s[w];
            unsigned wordbase = (unsigned)w << 10;
            while (cand) {
                int b = __ffsll((long long)cand) - 1;
                unsigned rowbase = wordbase + ((unsigned)b << 4);
                u64 bc = sup_s[rowbase + w];     // broadcast LDS: ON the chain
                u64 rv = sup_s[rowbase + lw];    // per-lane word: OFF the chain
                rem_own |= (lane < W) ? rv : 0;
                cand = (cand & (cand - 1)) & ~bc;
            }
        }
        if (lane < W) rem_s[lane] = rem_own;
    }
    __syncthreads();

    // Emit kept rows: [score, x1, y1, x2-x1, y2-y1]; rest already zero.
    for (int s = tid; s < M; s += bd) {
        if (!((rem_s[s >> 6] >> (s & 63)) & 1ull)) {
            u64 kk = g_skeys[s];
            float score = __uint_as_float(0xFFFFFFFFu - (unsigned int)(kk >> 32));
            float4 b = g_sboxes[s];
            float* o = out + 5 * s;
            o[0] = score;
            o[1] = b.x;
            o[2] = b.y;
            o[3] = b.z - b.x;
            o[4] = b.w - b.y;
        }
    }

    // Reset all cross-launch state for the next graph replay.
    if (tid < W) { g_allOR[tid] = 0; g_rowNZ[tid] = 0; }
    if (tid == 0) g_count = 0;
}

extern "C" void kernel_launch(void* const* d_in, const int* in_sizes, int n_in,
                              void* d_out, int out_size) {
    const float* o0 = (const float*)d_in[0];
    const float* o1 = (const float*)d_in[1];
    int P0 = (int)lround(sqrt((double)in_sizes[0] / 5.0));
    int P1 = (int)lround(sqrt((double)in_sizes[1] / 5.0));
    int N = P0 * P0 + P1 * P1;
    float* out = (float*)d_out;

    static int smem_set = 0;
    if (!smem_set) {
        cudaFuncSetAttribute(k_scan, cudaFuncAttributeMaxDynamicSharedMemorySize,
                             MAXM * W * (int)sizeof(u64));
        smem_set = 1;
    }

    int blocks = (N + 255) / 256;
    k_prep<<<blocks, 256>>>(o0, o1, P0, P1, out, out_size, N);
    k_sort<<<1, 1024>>>();
    k_matrix<<<(MAXM * W) / 256, 256>>>();
    k_scan<<<1, 1024, MAXM * W * (int)sizeof(u64)>>>(out);
}

// round 13
// speedup vs baseline: 1.2622x; 1.2622x over previous
#include <cuda_runtime.h>
#include <math.h>
#include <stdint.h>

#define MAXN 8192
#define MAXM 1024          // max valid boxes (E[M]~800, sigma~27; 8+ sigma headroom)
#define W    16            // 64-bit words per suppression row (MAXM/64)

typedef unsigned long long u64;

__device__ float4 g_boxes[MAXN];
__device__ u64 g_keys[MAXM];     // compacted valid keys (unsorted)
__device__ u64 g_skeys[MAXM];    // sorted keys
__device__ float4 g_sboxes[MAXM];
__device__ u64 g_sup[MAXM * W];  // suppression bit matrix (upper triangular)
__device__ u64 g_allOR[W];       // OR of all rows (cols with a suppressor)
__device__ u64 g_rowNZ[W];       // rows with any nonzero word
__device__ int g_count, g_c1;    // valid count + prep done-counter (k_scan resets)

// ---------------------------------------------------------------------------
// Kernel A: per-box prep (all blocks) + hybrid bitonic sort (last block).
// Fence scope is small (8 blocks); sort runs while other blocks drain.
// ---------------------------------------------------------------------------
__global__ void __launch_bounds__(1024, 1)
k_prep_sort(const float* __restrict__ o0, const float* __restrict__ o1,
            int P0, int P1, float* __restrict__ out, int out_size, int N) {
    const int tid = threadIdx.x;
    int n = blockIdx.x * 1024 + tid;
    int stride = gridDim.x * 1024;
    for (int t = n; t < out_size; t += stride) out[t] = 0.0f;

    if (n < N) {
        const float* src;
        int P, loc;
        int A0 = P0 * P0;
        if (n < A0) { src = o0; P = P0; loc = n; }
        else        { src = o1; P = P1; loc = n - A0; }
        int i = loc / P, j = loc - i * P;
        int A = P * P;

        float prob = src[0 * A + loc];
        float x1   = src[1 * A + loc];
        float x2   = src[2 * A + loc];
        float x3   = src[3 * A + loc];
        float x4   = src[4 * A + loc];

        float xps = 640.0f / (float)P;   // exact: 16 or 8
        float yps = 480.0f / (float)P;   // exact: 12 or 6
        bool m = prob > 0.9f;

        float c1 = m ? (x1 * xps + (float)i * xps) : x1;
        float c2 = m ? (x2 * yps + (float)j * yps) : x2;
        float c3 = m ? (x3 * 640.0f) : x3;
        float c4 = m ? (x4 * 480.0f) : x4;

        float X1 = rintf(c1);
        float Y1 = rintf(c2);
        float X2 = rintf(c3 + c1);
        float Y2 = rintf(c4 + c2);

        g_boxes[n] = make_float4(X1, Y1, X2, Y2);

        if (m) {
            int pos = atomicAdd(&g_count, 1);
            if (pos < MAXM) {
                unsigned int hi = 0xFFFFFFFFu - __float_as_uint(prob); // desc score
                g_keys[pos] = ((u64)hi << 32) | (unsigned int)n;       // tie: asc idx
            }
        }
    }

    // Last-block election (release: every thread fences its own stores).
    __threadfence();
    __syncthreads();
    __shared__ int flag;
    if (tid == 0) flag = (atomicAdd(&g_c1, 1) == (int)gridDim.x - 1);
    __syncthreads();
    if (!flag) return;

    // ---- hybrid bitonic sort (last block, P2=1024 with padding) ----
    int M = g_count; if (M > MAXM) M = MAXM;
    __shared__ u64 keys[MAXM];

    u64 v = (tid < M) ? __ldcg(&g_keys[tid]) : 0xFFFFFFFFFFFFFFFFull;

    // Stages k=2..32: fully intra-warp, zero barriers.
#pragma unroll
    for (int k = 2; k <= 32; k <<= 1) {
#pragma unroll
        for (int j = k >> 1; j >= 1; j >>= 1) {
            u64 p = __shfl_xor_sync(0xFFFFFFFFu, v, j);
            bool up = ((tid & k) == 0);
            bool keepmin = (((tid & j) == 0) == up);
            u64 lo = v < p ? v : p;
            u64 hi = v < p ? p : v;
            v = keepmin ? lo : hi;
        }
    }
    keys[tid] = v;
    __syncthreads();

    // Stages k=64..1024: smem for j>=32, shfl tail for j<=16.
    for (int k = 64; k <= 1024; k <<= 1) {
        for (int j = k >> 1; j >= 32; j >>= 1) {
            int ixj = tid ^ j;
            if (ixj > tid) {
                u64 a = keys[tid], b = keys[ixj];
                bool up = ((tid & k) == 0);
                if ((a > b) == up) { keys[tid] = b; keys[ixj] = a; }
            }
            __syncthreads();
        }
        v = keys[tid];
        bool up = ((tid & k) == 0);
#pragma unroll
        for (int j = 16; j >= 1; j >>= 1) {
            u64 p = __shfl_xor_sync(0xFFFFFFFFu, v, j);
            bool keepmin = (((tid & j) == 0) == up);
            u64 lo = v < p ? v : p;
            u64 hi = v < p ? p : v;
            v = keepmin ? lo : hi;
        }
        keys[tid] = v;
        __syncthreads();
    }

    if (tid < M) {
        u64 kk = keys[tid];
        g_skeys[tid] = kk;
        g_sboxes[tid] = g_boxes[(unsigned int)(kk & 0xFFFFFFFFu)];
    }
}

// ---------------------------------------------------------------------------
// K3: suppression bit matrix (upper triangular) + allOR/rowNZ summaries.
// Exact iou>0.5 via inter > 0.5*uni (all quantities integer-valued fp32).
// ---------------------------------------------------------------------------
__global__ void k_matrix() {
    int M = g_count; if (M > MAXM) M = MAXM;
    int t = blockIdx.x * blockDim.x + threadIdx.x;
    int i  = t >> 4;       // row
    int jw = t & (W - 1);  // word within row
    if (i >= M) return;

    int jbase = jw << 6;
    u64 word = 0;
    if (jbase + 64 > i + 1 && jbase < M) {
        float4 bi = g_sboxes[i];
        float ai = (bi.z - bi.x) * (bi.w - bi.y);
        int jend = min(jbase + 64, M);
        for (int j = max(jbase, i + 1); j < jend; ++j) {
            float4 bj = g_sboxes[j];
            float iw = fminf(bi.z, bj.z) - fmaxf(bi.x, bj.x);
            float ih = fminf(bi.w, bj.w) - fmaxf(bi.y, bj.y);
            iw = fmaxf(iw, 0.0f);
            ih = fmaxf(ih, 0.0f);
            float inter = iw * ih;
            float aj = (bj.z - bj.x) * (bj.w - bj.y);
            float uni = ai + aj - inter;
            if (uni > 0.0f && inter > 0.5f * uni)
                word |= 1ull << (j - jbase);
        }
    }
    g_sup[t] = word;
    if (word) {
        atomicOr(&g_allOR[jw], word);
        atomicOr(&g_rowNZ[i >> 6], 1ull << (i & 63));
    }
}

// ---------------------------------------------------------------------------
// K4 (R11 champion, frozen): sparse gather of nonzero rows + preOR; serial
// loop over suppressible suppressors; broadcast-LDS critical path.
// Emit kept rows; reset all state for next graph replay.
// ---------------------------------------------------------------------------
extern __shared__ u64 sup_s[];  // MAXM*W u64 = 128KB (only nonzero rows written)
__global__ void __launch_bounds__(1024, 1) k_scan(float* __restrict__ out) {
    __shared__ u64 allOR_s[W], rowNZ_s[W], preOR_s[W], rem_s[W];
    const int tid = threadIdx.x;
    const int bd  = 1024;

    int M = g_count; if (M > MAXM) M = MAXM;

    if (tid < W) {
        allOR_s[tid] = g_allOR[tid];
        rowNZ_s[tid] = g_rowNZ[tid];
        preOR_s[tid] = 0;
    }
    __syncthreads();

    // Gather ONLY nonzero rows into smem; fold preOR = OR of rows of
    // definitely-kept boxes (column bit not in allOR).
    u64 myPre = 0;
    int tot = M * W;
    for (int q = tid; q < tot; q += bd) {
        int ri = q >> 4;
        if ((rowNZ_s[ri >> 6] >> (ri & 63)) & 1ull) {
            u64 vv = g_sup[q];
            sup_s[q] = vv;
            if (!((allOR_s[ri >> 6] >> (ri & 63)) & 1ull)) myPre |= vv;
        }
    }
    myPre |= __shfl_xor_sync(0xFFFFFFFFu, myPre, 16);
    if ((tid & 31) < 16) atomicOr(&preOR_s[tid & 15], myPre);
    __syncthreads();

    // Serial warp loop over suppressible suppressors.
    if (tid < 32) {
        const int lane = tid;
        const int lw   = lane & 15;
        u64 rem_own = (lane < W) ? preOR_s[lane] : 0;
        int nwords = (M + 63) >> 6;

        for (int w = 0; w < nwords; ++w) {
            u64 remw = __shfl_sync(0xFFFFFFFFu, rem_own, w);
            u64 cand = allOR_s[w] & rowNZ_s[w] & ~remw;
            unsigned wordbase = (unsigned)w << 10;   // (w*64) << 4
            while (cand) {
                int b = __ffsll((long long)cand) - 1;
                unsigned rowbase = wordbase + ((unsigned)b << 4);
                u64 bc = sup_s[rowbase + w];     // broadcast LDS: ON the chain
                u64 rv = sup_s[rowbase + lw];    // per-lane word: OFF the chain
                rem_own |= (lane < W) ? rv : 0;
                cand = (cand & (cand - 1)) & ~bc;
            }
        }
        if (lane < W) rem_s[lane] = rem_own;
    }
    __syncthreads();

    // Emit kept rows: [score, x1, y1, x2-x1, y2-y1]; rest already zero.
    for (int s = tid; s < M; s += bd) {
        if (!((rem_s[s >> 6] >> (s & 63)) & 1ull)) {
            u64 kk = g_skeys[s];
            float score = __uint_as_float(0xFFFFFFFFu - (unsigned int)(kk >> 32));
            float4 b = g_sboxes[s];
            float* o = out + 5 * s;
            o[0] = score;
            o[1] = b.x;
            o[2] = b.y;
            o[3] = b.z - b.x;
            o[4] = b.w - b.y;
        }
    }

    // Reset all cross-launch state for the next graph replay.
    if (tid < W) { g_allOR[tid] = 0; g_rowNZ[tid] = 0; }
    if (tid == 0) { g_count = 0; g_c1 = 0; }
}

extern "C" void kernel_launch(void* const* d_in, const int* in_sizes, int n_in,
                              void* d_out, int out_size) {
    const float* o0 = (const float*)d_in[0];
    const float* o1 = (const float*)d_in[1];
    int P0 = (int)lround(sqrt((double)in_sizes[0] / 5.0));
    int P1 = (int)lround(sqrt((double)in_sizes[1] / 5.0));
    int N = P0 * P0 + P1 * P1;
    float* out = (float*)d_out;

    static int smem_set = 0;
    if (!smem_set) {
        cudaFuncSetAttribute(k_scan, cudaFuncAttributeMaxDynamicSharedMemorySize,
                             MAXM * W * (int)sizeof(u64));
        smem_set = 1;
    }

    int blocksA = (N + 1023) / 1024;                 // 8
    k_prep_sort<<<blocksA, 1024>>>(o0, o1, P0, P1, out, out_size, N);
    k_matrix<<<(MAXM * W) / 256, 256>>>();
    k_scan<<<1, 1024, MAXM * W * (int)sizeof(u64)>>>(out);
}